// round 5
// baseline (speedup 1.0000x reference)
#include <cuda_runtime.h>
#include <math.h>

#define NN 100000
#define NE 1600000
#define DD 128
#define CC 64
#define NL 4

// ---------------- scratch (device globals: allocation-free) ----------------
__device__ float g_h0[NN * DD];
__device__ float g_hA[NN * DD];
__device__ float g_hB[NN * DD];
__device__ float g_sup[NN * DD];
__device__ int   g_rowptr[NN + 1];
__device__ int   g_cursor[NN];
__device__ int   g_col[NE];
__device__ float g_val[NE];
__device__ int   g_bsum[128];

// ---------------- CSR build ----------------
__global__ void k_zero_rowptr() {
    int i = blockIdx.x * blockDim.x + threadIdx.x;
    if (i <= NN) g_rowptr[i] = 0;
}

__global__ void k_hist(const int* __restrict__ edst) {
    int i = blockIdx.x * blockDim.x + threadIdx.x;
    if (i < NE) atomicAdd(&g_rowptr[edst[i] + 1], 1);
}

// per-block inclusive scan over 1024 elements
__global__ void k_scan1() {
    __shared__ int sh[2][1024];
    int t = threadIdx.x;
    int i = blockIdx.x * 1024 + t;
    int v = (i <= NN) ? g_rowptr[i] : 0;
    sh[0][t] = v;
    __syncthreads();
    int p = 0;
    #pragma unroll
    for (int off = 1; off < 1024; off <<= 1) {
        int q = p ^ 1;
        int add = (t >= off) ? sh[p][t - off] : 0;
        sh[q][t] = sh[p][t] + add;
        __syncthreads();
        p = q;
    }
    if (i <= NN) g_rowptr[i] = sh[p][t];
    if (t == 1023) g_bsum[blockIdx.x] = sh[p][1023];
}

__global__ void k_scan2(int nb) {
    __shared__ int sh[128];
    int t = threadIdx.x;
    if (t < nb) sh[t] = g_bsum[t];
    __syncthreads();
    if (t == 0) {
        int s = 0;
        for (int b = 0; b < nb; b++) { s += sh[b]; sh[b] = s; }
    }
    __syncthreads();
    if (t < nb) g_bsum[t] = sh[t];
}

__global__ void k_scan3() {
    int t = threadIdx.x;
    int i = blockIdx.x * 1024 + t;
    if (i <= NN) {
        int v = g_rowptr[i];
        if (blockIdx.x > 0) v += g_bsum[blockIdx.x - 1];
        g_rowptr[i] = v;
        if (i < NN) g_cursor[i] = v;
    }
}

__global__ void k_fill(const int* __restrict__ esrc, const int* __restrict__ edst,
                       const float* __restrict__ ew) {
    int i = blockIdx.x * blockDim.x + threadIdx.x;
    if (i < NE) {
        int d = edst[i];
        int p = atomicAdd(&g_cursor[d], 1);
        g_col[p] = esrc[i];
        g_val[p] = ew[i];
    }
}

// ---------------- SpMM: support = 0.9*A@hin + 0.1*h0, warp-per-row ----------------
__global__ void k_spmm(const float* __restrict__ hin) {
    int gw = (blockIdx.x * blockDim.x + threadIdx.x) >> 5;
    int lane = threadIdx.x & 31;
    if (gw >= NN) return;
    int s = g_rowptr[gw], e = g_rowptr[gw + 1];
    const float4* h4 = (const float4*)hin;
    float4 acc = make_float4(0.f, 0.f, 0.f, 0.f);
    for (int i = s; i < e; i++) {
        int c = __ldg(&g_col[i]);
        float w = __ldg(&g_val[i]);
        float4 v = h4[c * 32 + lane];
        acc.x += w * v.x; acc.y += w * v.y; acc.z += w * v.z; acc.w += w * v.w;
    }
    const float4* h04 = (const float4*)g_h0;
    float4 z = h04[gw * 32 + lane];
    float4 r;
    r.x = 0.9f * acc.x + 0.1f * z.x;
    r.y = 0.9f * acc.y + 0.1f * z.y;
    r.z = 0.9f * acc.z + 0.1f * z.z;
    r.w = 0.9f * acc.w + 0.1f * z.w;
    ((float4*)g_sup)[gw * 32 + lane] = r;
}

// ---------------- GEMM: out = relu(c0*(A@W) + c1*A + hprev + bias) ----------------
// W: [128,128] row-major in shared (64KB). S tile: 64 rows (32KB). 8 rows/warp.
__global__ void __launch_bounds__(256, 2) k_gemm(
    const float* __restrict__ A, const float* __restrict__ W,
    const float* __restrict__ hprev, const float* __restrict__ bias,
    float* __restrict__ out, float c0, float c1)
{
    extern __shared__ float sh[];
    float* Wsh = sh;                 // 128*128
    float* Ssh = sh + DD * DD;       // 64*128
    int t = threadIdx.x;

    float4* Wsh4 = (float4*)Wsh;
    const float4* W4 = (const float4*)W;
    #pragma unroll
    for (int i = 0; i < 16; i++) Wsh4[t + i * 256] = W4[t + i * 256];

    int base = blockIdx.x * 64;
    float4* Ssh4 = (float4*)Ssh;
    const float4* A4 = (const float4*)A;
    #pragma unroll
    for (int i = 0; i < 8; i++) {
        int f = t + i * 256;           // float4 index in tile, 0..2047
        int row = base + (f >> 5);
        Ssh4[f] = (row < NN) ? A4[base * 32 + f] : make_float4(0.f, 0.f, 0.f, 0.f);
    }
    __syncthreads();

    int warp = t >> 5, lane = t & 31;
    int srow = warp * 8;

    float4 acc[8];
    #pragma unroll
    for (int r = 0; r < 8; r++) acc[r] = make_float4(0.f, 0.f, 0.f, 0.f);

    #pragma unroll 4
    for (int k = 0; k < DD; k++) {
        float4 w4 = Wsh4[k * 32 + lane];
        #pragma unroll
        for (int r = 0; r < 8; r++) {
            float sv = Ssh[(srow + r) * DD + k];
            acc[r].x += sv * w4.x;
            acc[r].y += sv * w4.y;
            acc[r].z += sv * w4.z;
            acc[r].w += sv * w4.w;
        }
    }

    const float4* hp4 = (const float4*)hprev;
    const float4* b4 = (const float4*)bias;
    #pragma unroll
    for (int r = 0; r < 8; r++) {
        int row = base + srow + r;
        if (row < NN) {
            float4 s4 = Ssh4[(srow + r) * 32 + lane];
            float4 o;
            o.x = c0 * acc[r].x + c1 * s4.x;
            o.y = c0 * acc[r].y + c1 * s4.y;
            o.z = c0 * acc[r].z + c1 * s4.z;
            o.w = c0 * acc[r].w + c1 * s4.w;
            if (hprev) {
                float4 h = hp4[row * 32 + lane];
                o.x += h.x; o.y += h.y; o.z += h.z; o.w += h.w;
            }
            if (bias) {
                float4 b = b4[lane];
                o.x += b.x; o.y += b.y; o.z += b.z; o.w += b.w;
            }
            o.x = fmaxf(o.x, 0.f); o.y = fmaxf(o.y, 0.f);
            o.z = fmaxf(o.z, 0.f); o.w = fmaxf(o.w, 0.f);
            ((float4*)out)[row * 32 + lane] = o;
        }
    }
}

// ---------------- output head: logits = h@w_out + b_out -> log_softmax ----------------
__global__ void k_out(const float* __restrict__ hin, const float* __restrict__ wout,
                      const float* __restrict__ bout, float* __restrict__ out)
{
    __shared__ float Wsh[DD * CC];   // 32KB
    __shared__ float Hsh[8][DD];     // 4KB
    int t = threadIdx.x;

    float4* Wsh4 = (float4*)Wsh;
    const float4* w4 = (const float4*)wout;
    #pragma unroll
    for (int i = 0; i < 8; i++) Wsh4[t + i * 256] = w4[t + i * 256];
    __syncthreads();

    int warp = t >> 5, lane = t & 31;
    int row = blockIdx.x * 8 + warp;
    if (row >= NN) return;

    ((float4*)Hsh[warp])[lane] = ((const float4*)hin)[row * 32 + lane];
    __syncwarp();

    float a0 = bout[2 * lane], a1 = bout[2 * lane + 1];
    const float2* Wsh2 = (const float2*)Wsh;
    #pragma unroll 4
    for (int k = 0; k < DD; k++) {
        float hv = Hsh[warp][k];
        float2 w = Wsh2[k * 32 + lane];
        a0 += hv * w.x;
        a1 += hv * w.y;
    }

    float m = fmaxf(a0, a1);
    #pragma unroll
    for (int off = 16; off; off >>= 1) m = fmaxf(m, __shfl_xor_sync(0xffffffffu, m, off));
    float se = expf(a0 - m) + expf(a1 - m);
    #pragma unroll
    for (int off = 16; off; off >>= 1) se += __shfl_xor_sync(0xffffffffu, se, off);
    float lse = m + logf(se);

    out[row * 64 + 2 * lane]     = a0 - lse;
    out[row * 64 + 2 * lane + 1] = a1 - lse;
}

// ---------------- launch ----------------
extern "C" void kernel_launch(void* const* d_in, const int* in_sizes, int n_in,
                              void* d_out, int out_size)
{
    const float* x     = (const float*)d_in[0];
    const int*   esrc  = (const int*)  d_in[1];
    const int*   edst  = (const int*)  d_in[2];
    const float* ew    = (const float*)d_in[3];
    const float* w_in  = (const float*)d_in[4];
    const float* b_in  = (const float*)d_in[5];
    const float* gcn_w = (const float*)d_in[6];
    const float* w_out = (const float*)d_in[7];
    const float* b_out = (const float*)d_in[8];
    float* out = (float*)d_out;

    const int GEMM_SMEM = (DD * DD + 64 * DD) * (int)sizeof(float); // 98304
    cudaFuncSetAttribute(k_gemm, cudaFuncAttributeMaxDynamicSharedMemorySize, GEMM_SMEM);

    void *ph0v, *phAv, *phBv, *psupv;
    cudaGetSymbolAddress(&ph0v, g_h0);
    cudaGetSymbolAddress(&phAv, g_hA);
    cudaGetSymbolAddress(&phBv, g_hB);
    cudaGetSymbolAddress(&psupv, g_sup);
    float* ph0 = (float*)ph0v;
    float* phA = (float*)phAv;
    float* phB = (float*)phBv;
    float* psup = (float*)psupv;

    const int NB = (NN + 1 + 1023) / 1024; // 98

    // CSR build (runs inside the graph each replay; cheap vs. 4 atomic SpMMs)
    k_zero_rowptr<<<(NN + 1 + 255) / 256, 256>>>();
    k_hist<<<(NE + 255) / 256, 256>>>(edst);
    k_scan1<<<NB, 1024>>>();
    k_scan2<<<1, 128>>>(NB);
    k_scan3<<<NB, 1024>>>();
    k_fill<<<(NE + 255) / 256, 256>>>(esrc, edst, ew);

    const int GB = (NN + 63) / 64;   // 1563 GEMM blocks
    const int SB = NN / 8;           // 12500 warp-per-row blocks (8 warps each)

    // h0 = relu(x @ w_in + b_in)
    k_gemm<<<GB, 256, GEMM_SMEM>>>(x, w_in, nullptr, b_in, ph0, 1.0f, 0.0f);

    float theta[NL];
    for (int l = 0; l < NL; l++) theta[l] = logf(0.5f / (float)(l + 2) + 1.0f);

    for (int l = 0; l < NL; l++) {
        float* hin  = (l == 0) ? ph0 : ((l & 1) ? phA : phB);
        float* hout = (l & 1) ? phB : phA;
        k_spmm<<<SB, 256>>>(hin);                       // g_sup = 0.9*A@hin + 0.1*h0
        k_gemm<<<GB, 256, GEMM_SMEM>>>(psup, gcn_w + l * DD * DD, hin, nullptr,
                                       hout, theta[l], 1.0f - theta[l]);
    }

    // final h is in g_hB (l=3 -> hout=phB)
    k_out<<<SB, 256>>>(phB, w_out, b_out, out);
}